// round 7
// baseline (speedup 1.0000x reference)
#include <cuda_runtime.h>
#include <cstdint>
#include <cstddef>

#define EPS   1e-6f
#define B_    16
#define NN    1024
#define FDIM  64
#define OUTD  128
#define KC    32
#define NITER (NN / KC)

// smem strides (floats). Conflict-free MMA fragment rules:
//   A-operand stride ≡ 4 (mod 32), B-operand stride ≡ 8 (mod 32)
#define SA_STR 36
#define SB_STR 136
#define OC_STR 196
#define SK_STR 136
#define RD_STR 132

// smem layout (float offsets)
#define OFF_ADIAG 0
#define OFF_INV   128
#define OFF_SROW  256
#define OFF_SALL  384
#define OFF_DYN   1408
#define ASTG      (128 * SA_STR)          // 4608
#define BSTG      (32 * SB_STR)           // 4352
#define GSTG      (ASTG + BSTG)           // 8960 per (group,buf)
#define OFF_PIPE(g, buf) (OFF_DYN + ((g) * 2 + (buf)) * GSTG)
#define OFF_OC    OFF_DYN                           // 128*196 = 25088
#define OFF_KM    (OFF_OC + 128 * OC_STR)           // 192*136 = 26112
#define OFF_RED   OFF_KM                            // 128*132 = 16896 (pre-Kmat)
#define SMEM_FLOATS (OFF_KM + 192 * SK_STR)         // 52608
#define SMEM_BYTES  (SMEM_FLOATS * 4)               // 210432

__device__ float g_inv[B_ * NN];
__device__ float g_s[B_ * NN];

__device__ __forceinline__ float to_tf32(float v) {
    float r;
    asm("cvt.rna.tf32.f32 %0, %1;" : "=f"(r) : "f"(v));
    return r;
}
__device__ __forceinline__ float4 tf32x4(float4 v) {
    v.x = to_tf32(v.x); v.y = to_tf32(v.y);
    v.z = to_tf32(v.z); v.w = to_tf32(v.w);
    return v;
}
__device__ __forceinline__ void mma_tf32(float* c, const uint32_t* a, const uint32_t* b) {
    asm volatile(
        "mma.sync.aligned.m16n8k8.row.col.f32.tf32.tf32.f32 "
        "{%0,%1,%2,%3}, {%4,%5,%6,%7}, {%8,%9}, {%0,%1,%2,%3};"
        : "+f"(c[0]), "+f"(c[1]), "+f"(c[2]), "+f"(c[3])
        : "r"(a[0]), "r"(a[1]), "r"(a[2]), "r"(a[3]), "r"(b[0]), "r"(b[1]));
}
__device__ __forceinline__ void group_bar(int id) {
    asm volatile("bar.sync %0, 256;" :: "r"(id) : "memory");
}

// ---------------------------------------------------------------------------
// Kernel 1: degree scalars. deg[b,i] = rowsum(A) - A[i,i] + 1
// ---------------------------------------------------------------------------
__global__ void deg_kernel(const float* __restrict__ A) {
    int warp = (blockIdx.x * blockDim.x + threadIdx.x) >> 5;
    int lane = threadIdx.x & 31;
    if (warp >= B_ * NN) return;
    const float* row = A + (size_t)warp * NN;
    float sum = 0.f;
    const float4* r4 = (const float4*)row;
#pragma unroll
    for (int w = 0; w < 8; w++) {
        float4 v = r4[w * 32 + lane];
        sum += v.x + v.y + v.z + v.w;
    }
#pragma unroll
    for (int off = 16; off > 0; off >>= 1)
        sum += __shfl_down_sync(0xFFFFFFFFu, sum, off);
    if (lane == 0) {
        float deg = sum - row[warp % NN] + 1.0f;
        g_inv[warp] = 1.0f / (EPS + deg);
        g_s[warp]   = 1.0f / (EPS + sqrtf(deg));
    }
}

// ---------------------------------------------------------------------------
// Kernel 2: fused, 512 threads = 2 split-K groups × 8 warps, warp tile 32x64.
// Each group owns a double-buffered pipeline with its own named barrier.
// ---------------------------------------------------------------------------
__global__ __launch_bounds__(512, 1)
void fused_mma_kernel(const float* __restrict__ A, const float* __restrict__ x,
                      const float* __restrict__ Kmat, const float* __restrict__ bias,
                      float* __restrict__ out) {
    extern __shared__ float sm[];
    const int tid  = threadIdx.x;
    const int wid  = tid >> 5;
    const int lane = tid & 31;
    const int b    = blockIdx.y;
    const int row0 = blockIdx.x * 128;

    const int grp = wid >> 3;          // 0 or 1 (split-K group)
    const int gt  = tid & 255;         // thread id within group
    const int w8  = wid & 7;           // warp id within group
    const int wm  = w8 >> 1;           // 0..3 : 32-row band
    const int wn  = w8 & 1;            // 0..1 : 64-col band of D
    const int m_base = wm * 32;
    const int lr = lane >> 2;          // 0..7
    const int lc = lane & 3;           // 0..3

    const float* Ab = A + (size_t)b * NN * NN;
    const float* xb = x + (size_t)b * NN * FDIM;

    // ---- per-row scalars + full s vector (needed for B staging)
#pragma unroll
    for (int i = tid; i < NN; i += 512) sm[OFF_SALL + i] = g_s[b * NN + i];
    if (tid < 128) {
        int grow = row0 + tid;
        sm[OFF_ADIAG + tid] = __ldg(&Ab[(size_t)grow * NN + grow]);
        sm[OFF_INV + tid]   = g_inv[b * NN + grow];
        sm[OFF_SROW + tid]  = g_s[b * NN + grow];
    }
    __syncthreads();

    // ---- staging geometry (per group: 256 threads stage 128x32 A + 32x128 B)
    const int ar = gt >> 3;            // 0..31 (A row base; +32j)
    const int ac = (gt & 7) * 4;       // A col within k-tile
    const int bk = gt >> 5;            // 0..7  (B k base; +8j)
    const int bc = (gt & 31) * 4;      // B col 0..124
    const bool bsc = (bc >= 64);       // scaled half
    const int bxf = bsc ? bc - 64 : bc;

    float acc[2][8][4];
#pragma unroll
    for (int mt = 0; mt < 2; mt++)
#pragma unroll
        for (int nt = 0; nt < 8; nt++)
#pragma unroll
            for (int q = 0; q < 4; q++) acc[mt][nt][q] = 0.f;

    // ---- stage first tile (kt = grp) into buf0
    {
        const int k0 = grp * KC;
        float* dA = &sm[OFF_PIPE(grp, 0)];
        float* dB = dA + ASTG;
#pragma unroll
        for (int j = 0; j < 4; j++) {
            int r = ar + 32 * j;
            float4 v = *(const float4*)&Ab[(size_t)(row0 + r) * NN + k0 + ac];
            *(float4*)&dA[r * SA_STR + ac] = tf32x4(v);
        }
#pragma unroll
        for (int j = 0; j < 4; j++) {
            int k = bk + 8 * j;
            float4 v = *(const float4*)&xb[(size_t)(k0 + k) * FDIM + bxf];
            if (bsc) {
                float sv = sm[OFF_SALL + k0 + k];
                v.x *= sv; v.y *= sv; v.z *= sv; v.w *= sv;
            }
            *(float4*)&dB[k * SB_STR + bc] = tf32x4(v);
        }
    }
    group_bar(1 + grp);

    // ---- mainloop: 16 k-tiles per group (kt = grp + 2*i)
    for (int i = 0; i < 16; ++i) {
        const float* sA = &sm[OFF_PIPE(grp, i & 1)];
        const float* sB = sA + ASTG;
#pragma unroll
        for (int ks = 0; ks < 4; ks++) {
            const int k = ks * 8;
            uint32_t af[2][4], bf[8][2];
#pragma unroll
            for (int mt = 0; mt < 2; mt++) {
                const float* p = sA + (m_base + mt * 16 + lr) * SA_STR + k + lc;
                af[mt][0] = __float_as_uint(p[0]);
                af[mt][1] = __float_as_uint(p[8 * SA_STR]);
                af[mt][2] = __float_as_uint(p[4]);
                af[mt][3] = __float_as_uint(p[8 * SA_STR + 4]);
            }
#pragma unroll
            for (int nt = 0; nt < 8; nt++) {
                const float* p = sB + (k + lc) * SB_STR + wn * 64 + nt * 8 + lr;
                bf[nt][0] = __float_as_uint(p[0]);
                bf[nt][1] = __float_as_uint(p[4 * SB_STR]);
            }
#pragma unroll
            for (int mt = 0; mt < 2; mt++)
#pragma unroll
                for (int nt = 0; nt < 8; nt++)
                    mma_tf32(acc[mt][nt], af[mt], bf[nt]);
        }
        if (i < 15) {
            const int kn = (grp + 2 * (i + 1)) * KC;
            float* dA = &sm[OFF_PIPE(grp, (i + 1) & 1)];
            float* dB = dA + ASTG;
#pragma unroll
            for (int j = 0; j < 4; j++) {
                int r = ar + 32 * j;
                float4 v = *(const float4*)&Ab[(size_t)(row0 + r) * NN + kn + ac];
                *(float4*)&dA[r * SA_STR + ac] = tf32x4(v);
            }
#pragma unroll
            for (int j = 0; j < 4; j++) {
                int k = bk + 8 * j;
                float4 v = *(const float4*)&xb[(size_t)(kn + k) * FDIM + bxf];
                if (bsc) {
                    float sv = sm[OFF_SALL + kn + k];
                    v.x *= sv; v.y *= sv; v.z *= sv; v.w *= sv;
                }
                *(float4*)&dB[k * SB_STR + bc] = tf32x4(v);
            }
        }
        group_bar(1 + grp);
    }
    __syncthreads();   // mainloop smem dead for both groups

    // ---- split-K reduction: g1 dumps acc, g0 adds
    if (grp == 1) {
#pragma unroll
        for (int mt = 0; mt < 2; mt++)
#pragma unroll
            for (int nt = 0; nt < 8; nt++)
#pragma unroll
                for (int h = 0; h < 2; h++) {
                    int r = m_base + mt * 16 + lr + h * 8;
                    int c = wn * 64 + nt * 8 + lc * 2;
                    *(float2*)&sm[OFF_RED + r * RD_STR + c] =
                        make_float2(acc[mt][nt][h * 2], acc[mt][nt][h * 2 + 1]);
                }
    }
    __syncthreads();
    if (grp == 0) {
#pragma unroll
        for (int mt = 0; mt < 2; mt++)
#pragma unroll
            for (int nt = 0; nt < 8; nt++)
#pragma unroll
                for (int h = 0; h < 2; h++) {
                    int r = m_base + mt * 16 + lr + h * 8;
                    int c = wn * 64 + nt * 8 + lc * 2;
                    float2 v = *(const float2*)&sm[OFF_RED + r * RD_STR + c];
                    acc[mt][nt][h * 2]     += v.x;
                    acc[mt][nt][h * 2 + 1] += v.y;
                }
    }
    __syncthreads();   // RED consumed; KM area free for Kmat

    // ---- g0: epilogue1 -> ocat [128][192] ; g1: stage Kmat (tf32)
    if (grp == 0) {
#pragma unroll
        for (int mt = 0; mt < 2; mt++) {
#pragma unroll
            for (int nt = 0; nt < 8; nt++) {
                const int f = nt * 8 + lc * 2;
#pragma unroll
                for (int h = 0; h < 2; h++) {
                    const int r = m_base + mt * 16 + lr + h * 8;
                    const float ad = sm[OFF_ADIAG + r];
                    const float c0 = acc[mt][nt][h * 2 + 0];
                    const float c1 = acc[mt][nt][h * 2 + 1];
                    float2 xv = *(const float2*)&xb[(size_t)(row0 + r) * FDIM + f];
                    if (wn == 0) {
                        const float inv = sm[OFF_INV + r];
                        float o1a = c0 - ad * xv.x;
                        float o1b = c1 - ad * xv.y;
                        float2 w1 = make_float2(to_tf32(o1a), to_tf32(o1b));
                        float2 w2 = make_float2(to_tf32(inv * (o1a + xv.x)),
                                                to_tf32(inv * (o1b + xv.y)));
                        *(float2*)&sm[OFF_OC + r * OC_STR + f]      = w1;
                        *(float2*)&sm[OFF_OC + r * OC_STR + 64 + f] = w2;
                    } else {
                        const float sv = sm[OFF_SROW + r];
                        const float t = sv * sv * (1.0f - ad);
                        float2 w3 = make_float2(to_tf32(sv * c0 + t * xv.x),
                                                to_tf32(sv * c1 + t * xv.y));
                        *(float2*)&sm[OFF_OC + r * OC_STR + 128 + f] = w3;
                    }
                }
            }
        }
    } else {
        const float4* src = (const float4*)Kmat;
#pragma unroll
        for (int i4 = gt; i4 < 192 * 128 / 4; i4 += 256) {
            int row = i4 >> 5, c4 = (i4 & 31) * 4;
            *(float4*)&sm[OFF_KM + row * SK_STR + c4] = tf32x4(src[i4]);
        }
    }
    __syncthreads();

    // ---- GEMM2: out[128,128] = ocat[128,192] @ Kmat[192,128]  (16 warps, 32x32)
    const int m4 = (wid >> 2) * 32;
    const int n4 = (wid & 3) * 32;
    float acc2[2][4][4];
#pragma unroll
    for (int mt = 0; mt < 2; mt++)
#pragma unroll
        for (int nt = 0; nt < 4; nt++)
#pragma unroll
            for (int q = 0; q < 4; q++) acc2[mt][nt][q] = 0.f;

#pragma unroll
    for (int ks = 0; ks < 24; ks++) {
        const int k = ks * 8;
        uint32_t af[2][4], bf[4][2];
#pragma unroll
        for (int mt = 0; mt < 2; mt++) {
            const float* p = &sm[OFF_OC + (m4 + mt * 16 + lr) * OC_STR + k + lc];
            af[mt][0] = __float_as_uint(p[0]);
            af[mt][1] = __float_as_uint(p[8 * OC_STR]);
            af[mt][2] = __float_as_uint(p[4]);
            af[mt][3] = __float_as_uint(p[8 * OC_STR + 4]);
        }
#pragma unroll
        for (int nt = 0; nt < 4; nt++) {
            const float* p = &sm[OFF_KM + (k + lc) * SK_STR + n4 + nt * 8 + lr];
            bf[nt][0] = __float_as_uint(p[0]);
            bf[nt][1] = __float_as_uint(p[4 * SK_STR]);
        }
#pragma unroll
        for (int mt = 0; mt < 2; mt++)
#pragma unroll
            for (int nt = 0; nt < 4; nt++)
                mma_tf32(acc2[mt][nt], af[mt], bf[nt]);
    }

    // ---- bias + relu + store
#pragma unroll
    for (int mt = 0; mt < 2; mt++) {
#pragma unroll
        for (int nt = 0; nt < 4; nt++) {
            const int col = n4 + nt * 8 + lc * 2;
            float2 bv = *(const float2*)&bias[col];
#pragma unroll
            for (int h = 0; h < 2; h++) {
                const int r = m4 + mt * 16 + lr + h * 8;
                float2 o;
                o.x = fmaxf(acc2[mt][nt][h * 2 + 0] + bv.x, 0.f);
                o.y = fmaxf(acc2[mt][nt][h * 2 + 1] + bv.y, 0.f);
                *(float2*)&out[((size_t)b * NN + row0 + r) * OUTD + col] = o;
            }
        }
    }
}

// ---------------------------------------------------------------------------
extern "C" void kernel_launch(void* const* d_in, const int* in_sizes, int n_in,
                              void* d_out, int out_size) {
    const float *x = nullptr, *A = nullptr, *Kmat = nullptr, *bias = nullptr;
    for (int i = 0; i < n_in; i++) {
        switch (in_sizes[i]) {
            case B_ * NN * FDIM:  x    = (const float*)d_in[i]; break;
            case B_ * NN * NN:    A    = (const float*)d_in[i]; break;
            case 3 * FDIM * OUTD: Kmat = (const float*)d_in[i]; break;
            case OUTD:            bias = (const float*)d_in[i]; break;
        }
    }
    float* out = (float*)d_out;

    static bool attr_set = false;
    if (!attr_set) {
        cudaFuncSetAttribute(fused_mma_kernel,
                             cudaFuncAttributeMaxDynamicSharedMemorySize, SMEM_BYTES);
        attr_set = true;
    }

    deg_kernel<<<(B_ * NN * 32 + 255) / 256, 256>>>(A);
    fused_mma_kernel<<<dim3(NN / 128, B_), 512, SMEM_BYTES>>>(A, x, Kmat, bias, out);
}